// round 5
// baseline (speedup 1.0000x reference)
#include <cuda_runtime.h>
#include <cuda_bf16.h>
#include <cstdint>

#define NB   64      // batch
#define TT   64      // seq len
#define NN   1024    // items
#define SS   32      // state dim
#define DD   32      // item dim
#define FF   64      // feature = SS + DD
#define GG   96      // 3 * SS
#define MAXDEG 96
#define BN   (NB * NN)

// Persistent state (module globals — no runtime allocation)
__device__ float g_h[BN * SS];          // (row, s) row-major
__device__ float g_Gi[GG * BN];         // TRANSPOSED: (g, row)
__device__ int   g_csc[NN * MAXDEG];    // in-neighbors of each v (zero-padded)
__device__ int   g_deg[NN];
__device__ float g_Cn[NN * DD];         // adj^T @ item_emb
// Folded weights
__device__ float g_M[192 * 128];        // [w_ih@w_in ; w_ih@w_out], original order
__device__ float g_MX_T[64 * 192];      // transposed, permuted-g: cols {h, agg}
__device__ float g_MC_T[64 * 192];      // transposed, permuted-g: merged / Cn cols
__device__ float g_Pc[NN * 192];        // per-node constant (permuted-g) incl. bias fold

__device__ __forceinline__ float sigmf(float x) {
    return 1.0f / (1.0f + __expf(-x));
}
__device__ __forceinline__ float tanhfast(float x) {
    float e = __expf(-2.0f * x);
    return (1.0f - e) / (1.0f + e);
}
__device__ __forceinline__ unsigned long long pack2(float lo, float hi) {
    unsigned long long r;
    asm("mov.b64 %0, {%1, %2};" : "=l"(r) : "f"(lo), "f"(hi));
    return r;
}
__device__ __forceinline__ void unpack2(unsigned long long v, float& lo, float& hi) {
    asm("mov.b64 {%0, %1}, %2;" : "=f"(lo), "=f"(hi) : "l"(v));
}
__device__ __forceinline__ unsigned long long ffma2(unsigned long long a,
                                                    unsigned long long b,
                                                    unsigned long long c) {
    unsigned long long d;
    asm("fma.rn.f32x2 %0, %1, %2, %3;" : "=l"(d) : "l"(a), "l"(b), "l"(c));
    return d;
}

// permuted g position: [in 0:48 | out 0:48 | in 48:96 | out 48:96]
__device__ __forceinline__ int gpos(int gg, int is_out) {
    return (gg / 48) * 96 + (is_out ? 48 : 0) + (gg % 48);
}

// ---------------------------------------------------------------------------
// Build CSC (zero-padded to MAXDEG)
// ---------------------------------------------------------------------------
__global__ void build_csc_kernel(const float* __restrict__ adj) {
    int v = blockIdx.x;
    int t = threadIdx.x;          // 256 threads, each handles 4 u's
    __shared__ int cnt[256];

    int base = t * 4;
    int flags = 0, c = 0;
    #pragma unroll
    for (int i = 0; i < 4; i++) {
        float a = adj[(base + i) * NN + v];
        if (a != 0.0f) { c++; flags |= (1 << i); }
    }
    cnt[t] = c;
    __syncthreads();
    for (int st = 1; st < 256; st <<= 1) {
        int val = cnt[t];
        int add = (t >= st) ? cnt[t - st] : 0;
        __syncthreads();
        cnt[t] = val + add;
        __syncthreads();
    }
    int off = cnt[t] - c;
    int total = cnt[255];
    int w = 0;
    #pragma unroll
    for (int i = 0; i < 4; i++) {
        if (flags & (1 << i)) {
            int idx = off + w;
            if (idx < MAXDEG) g_csc[v * MAXDEG + idx] = base + i;
            w++;
        }
    }
    int tot = (total < MAXDEG) ? total : MAXDEG;
    if (t == 0) g_deg[v] = tot;
    for (int p = tot + t; p < MAXDEG; p += 256) g_csc[v * MAXDEG + p] = 0;
}

__global__ void build_cn_kernel(const float* __restrict__ item_emb) {
    int v = blockIdx.x;
    int d = threadIdx.x;
    int deg = g_deg[v];
    float s = 0.0f;
    for (int k = 0; k < deg; k++) {
        int u = g_csc[v * MAXDEG + k];
        s += item_emb[u * DD + d];
    }
    g_Cn[v * DD + d] = s;
}

// ---------------------------------------------------------------------------
// M = [w_ih @ w_in ; w_ih @ w_out]  (192 x 128) + transposed/permuted slices
// ---------------------------------------------------------------------------
__global__ void build_M_kernel(const float* __restrict__ w_ih,
                               const float* __restrict__ w_in,
                               const float* __restrict__ w_out) {
    int idx = blockIdx.x;          // 0..191
    int k = threadIdx.x;           // 0..127
    int is_out = idx >= 96;
    int gg = idx % 96;
    int pos = gpos(gg, is_out);
    const float* wio = is_out ? w_out : w_in;
    float acc = 0.0f;
    #pragma unroll 8
    for (int o = 0; o < FF; o++) acc += w_ih[gg * FF + o] * wio[o * 128 + k];
    g_M[idx * 128 + k] = acc;
    if (k < 32)                 g_MX_T[k * 192 + pos] = acc;          // h cols
    else if (k >= 64 && k < 96) g_MX_T[(k - 32) * 192 + pos] = acc;   // agg cols
    else if (k >= 32 && k < 64) g_MC_T[(k - 32) * 192 + pos] = acc;   // merged cols
    else                        g_MC_T[(k - 96 + 32) * 192 + pos] = acc; // Cn cols
}

// Pc[v][pos] = M[:,32:64]@item_emb[v] + M[:,96:128]@Cn[v] + w_ih@bias
// 16 nodes per block; M slices register-cached per thread.
__global__ void __launch_bounds__(192) build_Pc_kernel(
    const float* __restrict__ item_emb,
    const float* __restrict__ w_ih,
    const float* __restrict__ b_in,
    const float* __restrict__ b_out) {
    int idx = threadIdx.x;   // 0..191
    int is_out = idx >= 96;
    int gg = idx % 96;
    int pos = gpos(gg, is_out);

    __shared__ float ie[16][32];
    __shared__ float cn[16][32];
    int v0 = blockIdx.x * 16;
    for (int i = idx; i < 16 * 32; i += 192) {
        int vv = i >> 5, d = i & 31;
        ie[vv][d] = item_emb[(v0 + vv) * DD + d];
        cn[vv][d] = g_Cn[(v0 + vv) * DD + d];
    }

    float m1[32], m2[32];
    #pragma unroll
    for (int k = 0; k < 32; k++) {
        m1[k] = g_M[idx * 128 + 32 + k];
        m2[k] = g_M[idx * 128 + 96 + k];
    }
    const float* bio = is_out ? b_out : b_in;
    float wb = 0.0f;
    #pragma unroll 8
    for (int o = 0; o < FF; o++) wb += w_ih[gg * FF + o] * bio[o];
    __syncthreads();

    for (int vv = 0; vv < 16; vv++) {
        float acc = wb;
        #pragma unroll
        for (int k = 0; k < 32; k++)
            acc += m1[k] * ie[vv][k] + m2[k] * cn[vv][k];
        g_Pc[(v0 + vv) * 192 + pos] = acc;
    }
}

__global__ void init_state_kernel(const float* __restrict__ b_ih) {
    int i = blockIdx.x * blockDim.x + threadIdx.x;
    if (i < GG * BN) g_Gi[i] = b_ih[i / BN];
    if (i < BN * SS) g_h[i] = 0.0f;
}

// ---------------------------------------------------------------------------
// Kernel A2: sparse Gi refresh.  grid (2, NB), 256 threads, warp-per-node.
// ---------------------------------------------------------------------------
__global__ void __launch_bounds__(256) step_sparse2(
    const int* __restrict__ item_ids, const int* __restrict__ responses, int t,
    const float* __restrict__ adj,
    const float* __restrict__ item_emb, const float* __restrict__ resp_emb,
    const float* __restrict__ in_a, const float* __restrict__ out_a,
    const float* __restrict__ b_ih)
{
    __shared__ float MXs[64 * 96];
    __shared__ float qS[96], qX[96];
    __shared__ float sdvec[32];
    __shared__ float xbuf[8][64];
    __shared__ float tbuf[8][96];

    int b = blockIdx.y, half = blockIdx.x;
    int tid = threadIdx.x, lane = tid & 31, w = tid >> 5;
    int item = item_ids[b * TT + t];
    int resp = responses[b * TT + t];
    int deg = g_deg[item];

    for (int i = tid; i < 64 * 96; i += 256) {
        int k = i / 96, o = i - k * 96;
        MXs[i] = g_MX_T[k * 192 + half * 96 + o];
    }
    if (tid < 32) sdvec[tid] = resp_emb[resp * DD + tid] - item_emb[item * DD + tid];
    __syncthreads();
    if (tid < 192) {
        int o = tid % 96;
        int isX = tid >= 96;
        const float* base = g_MC_T + (isX ? 32 * 192 : 0) + half * 96 + o;
        float acc = 0.0f;
        #pragma unroll
        for (int k = 0; k < 32; k++) acc += base[k * 192] * sdvec[k];
        if (isX) qX[o] = acc; else qS[o] = acc;
    }
    __syncthreads();

    const float* hb = g_h + (size_t)b * NN * SS;
    for (int j = w; j < deg; j += 8) {
        int v = g_csc[item * MAXDEG + j];
        // ---- gather agg = sum of in-neighbor h rows (unroll-8, MLP 8) ----
        float agg = 0.0f;
        int degv = g_deg[v];
        const int* nb = g_csc + v * MAXDEG;
        for (int k = 0; k < degv; k += 8) {
            #pragma unroll
            for (int i = 0; i < 8; i++) {
                int u = nb[k + i];
                float val = hb[u * SS + lane];
                if (k + i < degv) agg += val;
            }
        }
        xbuf[w][lane] = hb[v * SS + lane];
        xbuf[w][32 + lane] = agg;
        __syncwarp();

        bool hasrev = adj[(size_t)item * NN + v] != 0.0f;
        bool isself = (v == item);
        float a0 = g_Pc[v * 192 + half * 96 + lane];
        float a1 = g_Pc[v * 192 + half * 96 + 32 + lane];
        float a2 = g_Pc[v * 192 + half * 96 + 64 + lane];
        if (hasrev) { a0 += qX[lane]; a1 += qX[32 + lane]; a2 += qX[64 + lane]; }
        if (isself) { a0 += qS[lane]; a1 += qS[32 + lane]; a2 += qS[64 + lane]; }
        #pragma unroll
        for (int k = 0; k < 64; k++) {
            float xk = xbuf[w][k];
            a0 += MXs[k * 96 + lane]      * xk;
            a1 += MXs[k * 96 + 32 + lane] * xk;
            a2 += MXs[k * 96 + 64 + lane] * xk;
        }
        tbuf[w][lane] = a0;
        tbuf[w][32 + lane] = a1;
        tbuf[w][64 + lane] = a2;
        __syncwarp();

        float ia = in_a[v], oa = out_a[v];
        {
            int i = lane;                 // 0..31 (<48)
            int gg = half * 48 + i;
            float gi = b_ih[gg] + ia * tbuf[w][i] + oa * tbuf[w][48 + i];
            g_Gi[(size_t)gg * BN + b * NN + v] = gi;
        }
        if (lane < 16) {
            int i = 32 + lane;            // 32..47
            int gg = half * 48 + i;
            float gi = b_ih[gg] + ia * tbuf[w][i] + oa * tbuf[w][48 + i];
            g_Gi[(size_t)gg * BN + b * NN + v] = gi;
        }
        __syncwarp();
    }
}

// ---------------------------------------------------------------------------
// Kernel B3: packed-f32x2 GRU, 2 rows per thread, FULLY UNROLLED (no local
// memory). grid 128 x 256.
// ---------------------------------------------------------------------------
__global__ void __launch_bounds__(256, 1) step_gru2(
    const float* __restrict__ w_hh, const float* __restrict__ b_hh,
    const float* __restrict__ w_fc, const float* __restrict__ b_fc,
    float* __restrict__ out, int t, float* __restrict__ h_final)
{
    __shared__ __align__(16) unsigned long long whh2[GG * SS];   // {w,w} duplicated
    __shared__ float bhh[GG];
    __shared__ float wfc[SS];

    int tid = threadIdx.x;
    for (int i = tid; i < GG * SS; i += 256) {
        float wv = w_hh[i];
        whh2[i] = pack2(wv, wv);
    }
    if (tid < GG) bhh[tid] = b_hh[tid];
    if (tid < SS) wfc[tid] = w_fc[tid];
    __syncthreads();

    int i = blockIdx.x * 256 + tid;       // pair index 0..BN/2-1
    int r0 = 2 * i;

    unsigned long long hp[SS];
    {
        const float4* p0 = reinterpret_cast<const float4*>(g_h + (size_t)r0 * SS);
        const float4* p1 = reinterpret_cast<const float4*>(g_h + (size_t)(r0 + 1) * SS);
        #pragma unroll
        for (int q = 0; q < 8; q++) {
            float4 a = p0[q];
            float4 c = p1[q];
            hp[q * 4 + 0] = pack2(a.x, c.x);
            hp[q * 4 + 1] = pack2(a.y, c.y);
            hp[q * 4 + 2] = pack2(a.z, c.z);
            hp[q * 4 + 3] = pack2(a.w, c.w);
        }
    }

    const unsigned long long* gip = reinterpret_cast<const unsigned long long*>(g_Gi);
    const ulonglong2* whhv = reinterpret_cast<const ulonglong2*>(whh2);

    float hn0[SS], hn1[SS];
    float fc0 = 0.0f, fc1 = 0.0f;

    #pragma unroll
    for (int d = 0; d < SS; d++) {
        unsigned long long ar = 0ull, az = 0ull, an = 0ull;
        #pragma unroll
        for (int k = 0; k < SS; k += 2) {
            ulonglong2 wr = whhv[(d * SS + k) >> 1];
            ulonglong2 wz = whhv[((SS + d) * SS + k) >> 1];
            ulonglong2 wn = whhv[((2 * SS + d) * SS + k) >> 1];
            unsigned long long h2a = hp[k];
            unsigned long long h2b = hp[k + 1];
            ar = ffma2(wr.x, h2a, ar);
            az = ffma2(wz.x, h2a, az);
            an = ffma2(wn.x, h2a, an);
            ar = ffma2(wr.y, h2b, ar);
            az = ffma2(wz.y, h2b, az);
            an = ffma2(wn.y, h2b, an);
        }
        unsigned long long gr = gip[(size_t)d * (BN / 2) + i];
        unsigned long long gz = gip[(size_t)(SS + d) * (BN / 2) + i];
        unsigned long long gn = gip[(size_t)(2 * SS + d) * (BN / 2) + i];
        float arl, arh, azl, azh, anl, anh;
        float grl, grh, gzl, gzh, gnl, gnh, hl, hh;
        unpack2(ar, arl, arh);  unpack2(az, azl, azh);  unpack2(an, anl, anh);
        unpack2(gr, grl, grh);  unpack2(gz, gzl, gzh);  unpack2(gn, gnl, gnh);
        unpack2(hp[d], hl, hh);
        float br = bhh[d], bz = bhh[SS + d], bn = bhh[2 * SS + d];

        float r_l = sigmf(arl + br + grl);
        float r_h = sigmf(arh + br + grh);
        float z_l = sigmf(azl + bz + gzl);
        float z_h = sigmf(azh + bz + gzh);
        float n_l = tanhfast(gnl + r_l * (anl + bn));
        float n_h = tanhfast(gnh + r_h * (anh + bn));
        float h_l = (1.0f - z_l) * n_l + z_l * hl;
        float h_h = (1.0f - z_h) * n_h + z_h * hh;
        hn0[d] = h_l;
        hn1[d] = h_h;
        fc0 += h_l * wfc[d];
        fc1 += h_h * wfc[d];
    }

    int b0 = r0 >> 10;
    int v0 = r0 & (NN - 1);
    float bf = b_fc[0];
    out[((size_t)b0 * TT + t) * NN + v0]     = sigmf(fc0 + bf);
    out[((size_t)b0 * TT + t) * NN + v0 + 1] = sigmf(fc1 + bf);

    {
        float4* p0 = reinterpret_cast<float4*>(g_h + (size_t)r0 * SS);
        float4* p1 = reinterpret_cast<float4*>(g_h + (size_t)(r0 + 1) * SS);
        #pragma unroll
        for (int q = 0; q < 8; q++) {
            float4 a, c;
            a.x = hn0[q * 4 + 0]; a.y = hn0[q * 4 + 1];
            a.z = hn0[q * 4 + 2]; a.w = hn0[q * 4 + 3];
            c.x = hn1[q * 4 + 0]; c.y = hn1[q * 4 + 1];
            c.z = hn1[q * 4 + 2]; c.w = hn1[q * 4 + 3];
            p0[q] = a;
            p1[q] = c;
            if (h_final) {
                reinterpret_cast<float4*>(h_final + (size_t)r0 * SS)[q] = a;
                reinterpret_cast<float4*>(h_final + (size_t)(r0 + 1) * SS)[q] = c;
            }
        }
    }
}

// ---------------------------------------------------------------------------
extern "C" void kernel_launch(void* const* d_in, const int* in_sizes, int n_in,
                              void* d_out, int out_size) {
    const int*   item_ids  = (const int*)  d_in[0];
    const int*   responses = (const int*)  d_in[1];
    const float* adj       = (const float*)d_in[2];
    const float* item_emb  = (const float*)d_in[3];
    const float* resp_emb  = (const float*)d_in[4];
    const float* w_in      = (const float*)d_in[5];
    const float* b_in      = (const float*)d_in[6];
    const float* w_out     = (const float*)d_in[7];
    const float* b_out     = (const float*)d_in[8];
    const float* in_a      = (const float*)d_in[9];
    const float* out_a     = (const float*)d_in[10];
    const float* w_ih      = (const float*)d_in[11];
    const float* w_hh      = (const float*)d_in[12];
    const float* b_ih      = (const float*)d_in[13];
    const float* b_hh      = (const float*)d_in[14];
    const float* w_fc      = (const float*)d_in[15];
    const float* b_fc      = (const float*)d_in[16];

    float* out    = (float*)d_out;                       // (B, T, N)
    float* h_out  = out + (size_t)NB * TT * NN;          // (B, N, S)

    build_csc_kernel<<<NN, 256>>>(adj);
    build_cn_kernel<<<NN, 32>>>(item_emb);
    build_M_kernel<<<192, 128>>>(w_ih, w_in, w_out);
    build_Pc_kernel<<<NN / 16, 192>>>(item_emb, w_ih, b_in, b_out);
    {
        int total = GG * BN;
        init_state_kernel<<<(total + 255) / 256, 256>>>(b_ih);
    }

    for (int t = 0; t < TT; t++) {
        step_sparse2<<<dim3(2, NB), 256>>>(
            item_ids, responses, t, adj, item_emb, resp_emb,
            in_a, out_a, b_ih);
        step_gru2<<<BN / 512, 256>>>(
            w_hh, b_hh, w_fc, b_fc, out, t,
            (t == TT - 1) ? h_out : nullptr);
    }
}

// round 8
// speedup vs baseline: 1.3382x; 1.3382x over previous
#include <cuda_runtime.h>
#include <cuda_bf16.h>
#include <cstdint>

#define NB   64      // batch
#define TT   64      // seq len
#define NN   1024    // items
#define SS   32      // state dim
#define DD   32      // item dim
#define FF   64      // feature = SS + DD
#define GG   96      // 3 * SS
#define MAXDEG 96
#define BN   (NB * NN)

// Persistent state (module globals — no runtime allocation)
__device__ float g_h[BN * SS];          // (row, s) row-major
__device__ float g_Gi[GG * BN];         // TRANSPOSED: (g, row)
__device__ int   g_csc[NN * MAXDEG];    // in-neighbors of each v (zero-padded)
__device__ int   g_deg[NN];
__device__ float g_Cn[NN * DD];         // adj^T @ item_emb
// Folded weights
__device__ float g_M[192 * 128];        // [w_ih@w_in ; w_ih@w_out], original order
__device__ float g_MX_T[64 * 192];      // transposed, permuted-g: cols {h, agg}
__device__ float g_MC_T[64 * 192];      // transposed, permuted-g: merged / Cn cols
__device__ float g_Pc[NN * 192];        // per-node constant (permuted-g) incl. bias fold

__device__ __forceinline__ float sigmf(float x) {
    return 1.0f / (1.0f + __expf(-x));
}
__device__ __forceinline__ float tanhfast(float x) {
    float e = __expf(-2.0f * x);
    return (1.0f - e) / (1.0f + e);
}

// permuted g position: [in 0:48 | out 0:48 | in 48:96 | out 48:96]
__device__ __forceinline__ int gpos(int gg, int is_out) {
    return (gg / 48) * 96 + (is_out ? 48 : 0) + (gg % 48);
}

// ---------------------------------------------------------------------------
// Build CSC (zero-padded to MAXDEG)
// ---------------------------------------------------------------------------
__global__ void build_csc_kernel(const float* __restrict__ adj) {
    int v = blockIdx.x;
    int t = threadIdx.x;          // 256 threads, each handles 4 u's
    __shared__ int cnt[256];

    int base = t * 4;
    int flags = 0, c = 0;
    #pragma unroll
    for (int i = 0; i < 4; i++) {
        float a = adj[(base + i) * NN + v];
        if (a != 0.0f) { c++; flags |= (1 << i); }
    }
    cnt[t] = c;
    __syncthreads();
    for (int st = 1; st < 256; st <<= 1) {
        int val = cnt[t];
        int add = (t >= st) ? cnt[t - st] : 0;
        __syncthreads();
        cnt[t] = val + add;
        __syncthreads();
    }
    int off = cnt[t] - c;
    int total = cnt[255];
    int w = 0;
    #pragma unroll
    for (int i = 0; i < 4; i++) {
        if (flags & (1 << i)) {
            int idx = off + w;
            if (idx < MAXDEG) g_csc[v * MAXDEG + idx] = base + i;
            w++;
        }
    }
    int tot = (total < MAXDEG) ? total : MAXDEG;
    if (t == 0) g_deg[v] = tot;
    for (int p = tot + t; p < MAXDEG; p += 256) g_csc[v * MAXDEG + p] = 0;
}

__global__ void build_cn_kernel(const float* __restrict__ item_emb) {
    int v = blockIdx.x;
    int d = threadIdx.x;
    int deg = g_deg[v];
    float s = 0.0f;
    for (int k = 0; k < deg; k++) {
        int u = g_csc[v * MAXDEG + k];
        s += item_emb[u * DD + d];
    }
    g_Cn[v * DD + d] = s;
}

// ---------------------------------------------------------------------------
// M = [w_ih @ w_in ; w_ih @ w_out]  (192 x 128) + transposed/permuted slices
// ---------------------------------------------------------------------------
__global__ void build_M_kernel(const float* __restrict__ w_ih,
                               const float* __restrict__ w_in,
                               const float* __restrict__ w_out) {
    int idx = blockIdx.x;          // 0..191
    int k = threadIdx.x;           // 0..127
    int is_out = idx >= 96;
    int gg = idx % 96;
    int pos = gpos(gg, is_out);
    const float* wio = is_out ? w_out : w_in;
    float acc = 0.0f;
    #pragma unroll 8
    for (int o = 0; o < FF; o++) acc += w_ih[gg * FF + o] * wio[o * 128 + k];
    g_M[idx * 128 + k] = acc;
    if (k < 32)                 g_MX_T[k * 192 + pos] = acc;          // h cols
    else if (k >= 64 && k < 96) g_MX_T[(k - 32) * 192 + pos] = acc;   // agg cols
    else if (k >= 32 && k < 64) g_MC_T[(k - 32) * 192 + pos] = acc;   // merged cols
    else                        g_MC_T[(k - 96 + 32) * 192 + pos] = acc; // Cn cols
}

// Pc[v][pos] = M[:,32:64]@item_emb[v] + M[:,96:128]@Cn[v] + w_ih@bias
__global__ void __launch_bounds__(192) build_Pc_kernel(
    const float* __restrict__ item_emb,
    const float* __restrict__ w_ih,
    const float* __restrict__ b_in,
    const float* __restrict__ b_out) {
    int idx = threadIdx.x;   // 0..191
    int is_out = idx >= 96;
    int gg = idx % 96;
    int pos = gpos(gg, is_out);

    __shared__ float ie[16][32];
    __shared__ float cn[16][32];
    int v0 = blockIdx.x * 16;
    for (int i = idx; i < 16 * 32; i += 192) {
        int vv = i >> 5, d = i & 31;
        ie[vv][d] = item_emb[(v0 + vv) * DD + d];
        cn[vv][d] = g_Cn[(v0 + vv) * DD + d];
    }

    float m1[32], m2[32];
    #pragma unroll
    for (int k = 0; k < 32; k++) {
        m1[k] = g_M[idx * 128 + 32 + k];
        m2[k] = g_M[idx * 128 + 96 + k];
    }
    const float* bio = is_out ? b_out : b_in;
    float wb = 0.0f;
    #pragma unroll 8
    for (int o = 0; o < FF; o++) wb += w_ih[gg * FF + o] * bio[o];
    __syncthreads();

    for (int vv = 0; vv < 16; vv++) {
        float acc = wb;
        #pragma unroll
        for (int k = 0; k < 32; k++)
            acc += m1[k] * ie[vv][k] + m2[k] * cn[vv][k];
        g_Pc[(v0 + vv) * 192 + pos] = acc;
    }
}

__global__ void init_state_kernel(const float* __restrict__ b_ih) {
    int i = blockIdx.x * blockDim.x + threadIdx.x;
    if (i < GG * BN) g_Gi[i] = b_ih[i / BN];
    if (i < BN * SS) g_h[i] = 0.0f;
}

// ---------------------------------------------------------------------------
// Kernel A2: sparse Gi refresh.  grid (2, NB), 256 threads, warp-per-node.
// ---------------------------------------------------------------------------
__global__ void __launch_bounds__(256) step_sparse2(
    const int* __restrict__ item_ids, const int* __restrict__ responses, int t,
    const float* __restrict__ adj,
    const float* __restrict__ item_emb, const float* __restrict__ resp_emb,
    const float* __restrict__ in_a, const float* __restrict__ out_a,
    const float* __restrict__ b_ih)
{
    __shared__ float MXs[64 * 96];
    __shared__ float qS[96], qX[96];
    __shared__ float sdvec[32];
    __shared__ float xbuf[8][64];
    __shared__ float tbuf[8][96];

    int b = blockIdx.y, half = blockIdx.x;
    int tid = threadIdx.x, lane = tid & 31, w = tid >> 5;
    int item = item_ids[b * TT + t];
    int resp = responses[b * TT + t];
    int deg = g_deg[item];

    for (int i = tid; i < 64 * 96; i += 256) {
        int k = i / 96, o = i - k * 96;
        MXs[i] = g_MX_T[k * 192 + half * 96 + o];
    }
    if (tid < 32) sdvec[tid] = resp_emb[resp * DD + tid] - item_emb[item * DD + tid];
    __syncthreads();
    if (tid < 192) {
        int o = tid % 96;
        int isX = tid >= 96;
        const float* base = g_MC_T + (isX ? 32 * 192 : 0) + half * 96 + o;
        float acc = 0.0f;
        #pragma unroll
        for (int k = 0; k < 32; k++) acc += base[k * 192] * sdvec[k];
        if (isX) qX[o] = acc; else qS[o] = acc;
    }
    __syncthreads();

    const float* hb = g_h + (size_t)b * NN * SS;
    for (int j = w; j < deg; j += 8) {
        int v = g_csc[item * MAXDEG + j];
        // ---- gather agg = sum of in-neighbor h rows (unroll-8, MLP 8) ----
        float agg = 0.0f;
        int degv = g_deg[v];
        const int* nb = g_csc + v * MAXDEG;
        for (int k = 0; k < degv; k += 8) {
            #pragma unroll
            for (int i = 0; i < 8; i++) {
                int u = nb[k + i];
                float val = hb[u * SS + lane];
                if (k + i < degv) agg += val;
            }
        }
        xbuf[w][lane] = hb[v * SS + lane];
        xbuf[w][32 + lane] = agg;
        __syncwarp();

        bool hasrev = adj[(size_t)item * NN + v] != 0.0f;
        bool isself = (v == item);
        float a0 = g_Pc[v * 192 + half * 96 + lane];
        float a1 = g_Pc[v * 192 + half * 96 + 32 + lane];
        float a2 = g_Pc[v * 192 + half * 96 + 64 + lane];
        if (hasrev) { a0 += qX[lane]; a1 += qX[32 + lane]; a2 += qX[64 + lane]; }
        if (isself) { a0 += qS[lane]; a1 += qS[32 + lane]; a2 += qS[64 + lane]; }
        #pragma unroll
        for (int k = 0; k < 64; k++) {
            float xk = xbuf[w][k];
            a0 += MXs[k * 96 + lane]      * xk;
            a1 += MXs[k * 96 + 32 + lane] * xk;
            a2 += MXs[k * 96 + 64 + lane] * xk;
        }
        tbuf[w][lane] = a0;
        tbuf[w][32 + lane] = a1;
        tbuf[w][64 + lane] = a2;
        __syncwarp();

        float ia = in_a[v], oa = out_a[v];
        {
            int i = lane;                 // 0..31 (<48)
            int gg = half * 48 + i;
            float gi = b_ih[gg] + ia * tbuf[w][i] + oa * tbuf[w][48 + i];
            g_Gi[(size_t)gg * BN + b * NN + v] = gi;
        }
        if (lane < 16) {
            int i = 32 + lane;            // 32..47
            int gg = half * 48 + i;
            float gi = b_ih[gg] + ia * tbuf[w][i] + oa * tbuf[w][48 + i];
            g_Gi[(size_t)gg * BN + b * NN + v] = gi;
        }
        __syncwarp();
    }
}

// ---------------------------------------------------------------------------
// Kernel B4: GRU, one row per thread, float4 shared weight loads, fully
// unrolled, low register pressure (no hnew array). grid 256 x 256.
// ---------------------------------------------------------------------------
__global__ void __launch_bounds__(256) step_gru4(
    const float* __restrict__ w_hh, const float* __restrict__ b_hh,
    const float* __restrict__ w_fc, const float* __restrict__ b_fc,
    float* __restrict__ out, int t, float* __restrict__ h_final)
{
    __shared__ __align__(16) float whh[GG * SS];
    __shared__ float bhh[GG];
    __shared__ float wfc[SS];

    int tid = threadIdx.x;
    for (int i = tid; i < GG * SS; i += 256) whh[i] = w_hh[i];
    if (tid < GG) bhh[tid] = b_hh[tid];
    if (tid < SS) wfc[tid] = w_fc[tid];
    __syncthreads();

    const float4* whh4 = reinterpret_cast<const float4*>(whh);

    int r = blockIdx.x * 256 + tid;

    // load h row (8x LDG.128)
    float h[SS];
    {
        const float4* hp = reinterpret_cast<const float4*>(g_h + (size_t)r * SS);
        #pragma unroll
        for (int q = 0; q < 8; q++) {
            float4 hv = hp[q];
            h[q * 4 + 0] = hv.x; h[q * 4 + 1] = hv.y;
            h[q * 4 + 2] = hv.z; h[q * 4 + 3] = hv.w;
        }
    }

    float4* hrow  = reinterpret_cast<float4*>(g_h + (size_t)r * SS);
    float4* hfrow = h_final ? reinterpret_cast<float4*>(h_final + (size_t)r * SS)
                            : nullptr;

    float fc = 0.0f;
    float o0, o1, o2, o3;   // staging for float4 h stores (d is compile-time)

    #pragma unroll
    for (int d = 0; d < SS; d++) {
        float ar = bhh[d], az = bhh[SS + d], an = bhh[2 * SS + d];
        #pragma unroll
        for (int q = 0; q < 8; q++) {
            float4 wr = whh4[(d * SS) / 4 + q];
            float4 wz = whh4[((SS + d) * SS) / 4 + q];
            float4 wn = whh4[((2 * SS + d) * SS) / 4 + q];
            float h0 = h[q * 4 + 0], h1 = h[q * 4 + 1];
            float h2 = h[q * 4 + 2], h3 = h[q * 4 + 3];
            ar += wr.x * h0 + wr.y * h1 + wr.z * h2 + wr.w * h3;
            az += wz.x * h0 + wz.y * h1 + wz.z * h2 + wz.w * h3;
            an += wn.x * h0 + wn.y * h1 + wn.z * h2 + wn.w * h3;
        }
        float gr = g_Gi[(size_t)d * BN + r];
        float gz = g_Gi[(size_t)(SS + d) * BN + r];
        float gn = g_Gi[(size_t)(2 * SS + d) * BN + r];
        float rr = sigmf(ar + gr);
        float zz = sigmf(az + gz);
        float nn = tanhfast(gn + rr * an);
        float hn = (1.0f - zz) * nn + zz * h[d];
        fc += hn * wfc[d];
        // stage into float4 (d constant after unroll)
        if ((d & 3) == 0) o0 = hn;
        else if ((d & 3) == 1) o1 = hn;
        else if ((d & 3) == 2) o2 = hn;
        else {
            o3 = hn;
            float4 ov; ov.x = o0; ov.y = o1; ov.z = o2; ov.w = o3;
            hrow[d / 4] = ov;
            if (hfrow) hfrow[d / 4] = ov;
        }
    }

    int b0 = r >> 10;
    int v0 = r & (NN - 1);
    out[((size_t)b0 * TT + t) * NN + v0] = sigmf(fc + b_fc[0]);
}

// ---------------------------------------------------------------------------
extern "C" void kernel_launch(void* const* d_in, const int* in_sizes, int n_in,
                              void* d_out, int out_size) {
    const int*   item_ids  = (const int*)  d_in[0];
    const int*   responses = (const int*)  d_in[1];
    const float* adj       = (const float*)d_in[2];
    const float* item_emb  = (const float*)d_in[3];
    const float* resp_emb  = (const float*)d_in[4];
    const float* w_in      = (const float*)d_in[5];
    const float* b_in      = (const float*)d_in[6];
    const float* w_out     = (const float*)d_in[7];
    const float* b_out     = (const float*)d_in[8];
    const float* in_a      = (const float*)d_in[9];
    const float* out_a     = (const float*)d_in[10];
    const float* w_ih      = (const float*)d_in[11];
    const float* w_hh      = (const float*)d_in[12];
    const float* b_ih      = (const float*)d_in[13];
    const float* b_hh      = (const float*)d_in[14];
    const float* w_fc      = (const float*)d_in[15];
    const float* b_fc      = (const float*)d_in[16];

    float* out    = (float*)d_out;                       // (B, T, N)
    float* h_out  = out + (size_t)NB * TT * NN;          // (B, N, S)

    build_csc_kernel<<<NN, 256>>>(adj);
    build_cn_kernel<<<NN, 32>>>(item_emb);
    build_M_kernel<<<192, 128>>>(w_ih, w_in, w_out);
    build_Pc_kernel<<<NN / 16, 192>>>(item_emb, w_ih, b_in, b_out);
    {
        int total = GG * BN;
        init_state_kernel<<<(total + 255) / 256, 256>>>(b_ih);
    }

    for (int t = 0; t < TT; t++) {
        step_sparse2<<<dim3(2, NB), 256>>>(
            item_ids, responses, t, adj, item_emb, resp_emb,
            in_a, out_a, b_ih);
        step_gru4<<<BN / 256, 256>>>(
            w_hh, b_hh, w_fc, b_fc, out, t,
            (t == TT - 1) ? h_out : nullptr);
    }
}

// round 12
// speedup vs baseline: 1.7998x; 1.3450x over previous
#include <cuda_runtime.h>
#include <cuda_bf16.h>
#include <cstdint>

#define NB   64      // batch
#define TT   64      // seq len
#define NN   1024    // items
#define SS   32      // state dim
#define DD   32      // item dim
#define FF   64      // feature = SS + DD
#define GG   96      // 3 * SS
#define MAXDEG 96
#define CSCPAD 112   // padded stride so unroll-16 gather never reads OOB
#define BN   (NB * NN)

// Persistent state (module globals — no runtime allocation)
__device__ float g_h[BN * SS];          // (row, s) row-major
__device__ float g_Gi[GG * BN];         // TRANSPOSED: (g, row)
__device__ int   g_csc[NN * CSCPAD];    // in-neighbors of each v (zero-padded)
__device__ int   g_deg[NN];
__device__ float g_Cn[NN * DD];         // adj^T @ item_emb
// Folded weights
__device__ float g_M[192 * 128];        // [w_ih@w_in ; w_ih@w_out], original order
__device__ float g_MX_T[64 * 192];      // transposed, permuted-g: cols {h, agg}
__device__ float g_MC_T[64 * 192];      // transposed, permuted-g: merged / Cn cols
__device__ float g_Pc[NN * 192];        // per-node constant (permuted-g) incl. bias fold

__device__ __forceinline__ float sigmf(float x) {
    return 1.0f / (1.0f + __expf(-x));
}
__device__ __forceinline__ float tanhfast(float x) {
    float e = __expf(-2.0f * x);
    return (1.0f - e) / (1.0f + e);
}

// permuted g position: [in 0:48 | out 0:48 | in 48:96 | out 48:96]
__device__ __forceinline__ int gpos(int gg, int is_out) {
    return (gg / 48) * 96 + (is_out ? 48 : 0) + (gg % 48);
}

// ---------------------------------------------------------------------------
// Build CSC (zero-padded to CSCPAD)
// ---------------------------------------------------------------------------
__global__ void build_csc_kernel(const float* __restrict__ adj) {
    int v = blockIdx.x;
    int t = threadIdx.x;          // 256 threads, each handles 4 u's
    __shared__ int cnt[256];

    int base = t * 4;
    int flags = 0, c = 0;
    #pragma unroll
    for (int i = 0; i < 4; i++) {
        float a = adj[(base + i) * NN + v];
        if (a != 0.0f) { c++; flags |= (1 << i); }
    }
    cnt[t] = c;
    __syncthreads();
    for (int st = 1; st < 256; st <<= 1) {
        int val = cnt[t];
        int add = (t >= st) ? cnt[t - st] : 0;
        __syncthreads();
        cnt[t] = val + add;
        __syncthreads();
    }
    int off = cnt[t] - c;
    int total = cnt[255];
    int w = 0;
    #pragma unroll
    for (int i = 0; i < 4; i++) {
        if (flags & (1 << i)) {
            int idx = off + w;
            if (idx < MAXDEG) g_csc[v * CSCPAD + idx] = base + i;
            w++;
        }
    }
    int tot = (total < MAXDEG) ? total : MAXDEG;
    if (t == 0) g_deg[v] = tot;
    for (int p = tot + t; p < CSCPAD; p += 256) g_csc[v * CSCPAD + p] = 0;
}

__global__ void build_cn_kernel(const float* __restrict__ item_emb) {
    int v = blockIdx.x;
    int d = threadIdx.x;
    int deg = g_deg[v];
    float s = 0.0f;
    for (int k = 0; k < deg; k++) {
        int u = g_csc[v * CSCPAD + k];
        s += item_emb[u * DD + d];
    }
    g_Cn[v * DD + d] = s;
}

// ---------------------------------------------------------------------------
// M = [w_ih @ w_in ; w_ih @ w_out]  (192 x 128) + transposed/permuted slices
// ---------------------------------------------------------------------------
__global__ void build_M_kernel(const float* __restrict__ w_ih,
                               const float* __restrict__ w_in,
                               const float* __restrict__ w_out) {
    int idx = blockIdx.x;          // 0..191
    int k = threadIdx.x;           // 0..127
    int is_out = idx >= 96;
    int gg = idx % 96;
    int pos = gpos(gg, is_out);
    const float* wio = is_out ? w_out : w_in;
    float acc = 0.0f;
    #pragma unroll 8
    for (int o = 0; o < FF; o++) acc += w_ih[gg * FF + o] * wio[o * 128 + k];
    g_M[idx * 128 + k] = acc;
    if (k < 32)                 g_MX_T[k * 192 + pos] = acc;          // h cols
    else if (k >= 64 && k < 96) g_MX_T[(k - 32) * 192 + pos] = acc;   // agg cols
    else if (k >= 32 && k < 64) g_MC_T[(k - 32) * 192 + pos] = acc;   // merged cols
    else                        g_MC_T[(k - 96 + 32) * 192 + pos] = acc; // Cn cols
}

// Pc[v][pos] = M[:,32:64]@item_emb[v] + M[:,96:128]@Cn[v] + w_ih@bias
__global__ void __launch_bounds__(192) build_Pc_kernel(
    const float* __restrict__ item_emb,
    const float* __restrict__ w_ih,
    const float* __restrict__ b_in,
    const float* __restrict__ b_out) {
    int idx = threadIdx.x;   // 0..191
    int is_out = idx >= 96;
    int gg = idx % 96;
    int pos = gpos(gg, is_out);

    __shared__ float ie[16][32];
    __shared__ float cn[16][32];
    int v0 = blockIdx.x * 16;
    for (int i = idx; i < 16 * 32; i += 192) {
        int vv = i >> 5, d = i & 31;
        ie[vv][d] = item_emb[(v0 + vv) * DD + d];
        cn[vv][d] = g_Cn[(v0 + vv) * DD + d];
    }

    float m1[32], m2[32];
    #pragma unroll
    for (int k = 0; k < 32; k++) {
        m1[k] = g_M[idx * 128 + 32 + k];
        m2[k] = g_M[idx * 128 + 96 + k];
    }
    const float* bio = is_out ? b_out : b_in;
    float wb = 0.0f;
    #pragma unroll 8
    for (int o = 0; o < FF; o++) wb += w_ih[gg * FF + o] * bio[o];
    __syncthreads();

    for (int vv = 0; vv < 16; vv++) {
        float acc = wb;
        #pragma unroll
        for (int k = 0; k < 32; k++)
            acc += m1[k] * ie[vv][k] + m2[k] * cn[vv][k];
        g_Pc[(v0 + vv) * 192 + pos] = acc;
    }
}

__global__ void init_state_kernel(const float* __restrict__ b_ih) {
    int i = blockIdx.x * blockDim.x + threadIdx.x;
    if (i < GG * BN) g_Gi[i] = b_ih[i / BN];
    if (i < BN * SS) g_h[i] = 0.0f;
}

// ---------------------------------------------------------------------------
// Kernel A3: sparse Gi refresh, fused halves.
// Grid: NB blocks x 512 threads (16 warps); warp-per-node, ~2 nodes/warp.
// Dynamic shared layout (floats):
//   [0)         MXs   64*192 = 12288
//   [12288)     tbuf  16*192 = 3072
//   [15360)     xbuf  16*64  = 1024
//   [16384)     qS 192 | qX 192 | sdvec 32 | bihs 96   (=512)
// total 16896 floats = 67584 bytes
// ---------------------------------------------------------------------------
#define SP3_SMEM_FLOATS 16896
#define SP3_SMEM_BYTES  (SP3_SMEM_FLOATS * 4)

__global__ void __launch_bounds__(512) step_sparse3(
    const int* __restrict__ item_ids, const int* __restrict__ responses, int t,
    const float* __restrict__ adj,
    const float* __restrict__ item_emb, const float* __restrict__ resp_emb,
    const float* __restrict__ in_a, const float* __restrict__ out_a,
    const float* __restrict__ b_ih)
{
    extern __shared__ float smem[];
    float* MXs   = smem;                 // [64][192]
    float* tbufA = smem + 12288;         // [16][192]
    float* xbufA = smem + 15360;         // [16][64]
    float* qS    = smem + 16384;         // [192]
    float* qX    = qS + 192;             // [192]
    float* sdvec = qX + 192;             // [32]
    float* bihs  = sdvec + 32;           // [96]

    int b = blockIdx.x;
    int tid = threadIdx.x, lane = tid & 31, w = tid >> 5;
    int item = item_ids[b * TT + t];
    int resp = responses[b * TT + t];
    int deg = g_deg[item];

    // prologue: weights + small vectors
    for (int i = tid; i < 64 * 192; i += 512) MXs[i] = g_MX_T[i];
    if (tid < 32) sdvec[tid] = resp_emb[resp * DD + tid] - item_emb[item * DD + tid];
    if (tid >= 64 && tid < 160) bihs[tid - 64] = b_ih[tid - 64];
    __syncthreads();
    // qS/qX over the FULL 192-wide permuted dimension (384 threads)
    if (tid < 384) {
        int pos = (tid >= 192) ? (tid - 192) : tid;
        int isX = tid >= 192;
        const float* base = g_MC_T + (isX ? 32 * 192 : 0) + pos;
        float acc = 0.0f;
        #pragma unroll
        for (int k = 0; k < 32; k++) acc += base[k * 192] * sdvec[k];
        if (isX) qX[pos] = acc; else qS[pos] = acc;
    }
    __syncthreads();

    const float* hb = g_h + (size_t)b * NN * SS;
    float* xb = xbufA + w * 64;
    float* tb = tbufA + w * 192;

    for (int j = w; j < deg; j += 16) {
        int v = g_csc[item * CSCPAD + j];

        // ---- gather agg: 16 loads in flight, 2 accumulator chains ----
        int degv = g_deg[v];
        const int* nb = g_csc + v * CSCPAD;
        float acc0 = 0.0f, acc1 = 0.0f;
        for (int k = 0; k < degv; k += 16) {
            #pragma unroll
            for (int i = 0; i < 16; i += 2) {
                int u0 = nb[k + i];
                int u1 = nb[k + i + 1];
                float x0 = hb[u0 * SS + lane];
                float x1 = hb[u1 * SS + lane];
                if (k + i < degv)     acc0 += x0;
                if (k + i + 1 < degv) acc1 += x1;
            }
        }
        float hv = hb[v * SS + lane];
        xb[lane] = hv;
        xb[32 + lane] = acc0 + acc1;
        __syncwarp();

        // ---- 192x64 matvec: lane owns 6 outputs (pos = lane + 32m) ----
        bool hasrev = adj[(size_t)item * NN + v] != 0.0f;
        bool isself = (v == item);
        float acc[6];
        #pragma unroll
        for (int m = 0; m < 6; m++) {
            int pos = lane + 32 * m;
            float a = g_Pc[v * 192 + pos];
            if (hasrev) a += qX[pos];
            if (isself) a += qS[pos];
            acc[m] = a;
        }
        #pragma unroll
        for (int k = 0; k < 64; k++) {
            float xk = xb[k];
            #pragma unroll
            for (int m = 0; m < 6; m++)
                acc[m] += MXs[k * 192 + lane + 32 * m] * xk;
        }
        #pragma unroll
        for (int m = 0; m < 6; m++) tb[lane + 32 * m] = acc[m];
        __syncwarp();

        // ---- epilogue: Gi[gg] = b_ih + in_a*t_in + out_a*t_out ----
        float ia = in_a[v], oa = out_a[v];
        #pragma unroll
        for (int m = 0; m < 3; m++) {
            int gg = lane + 32 * m;
            int q = (gg >= 48) ? 1 : 0;
            int pos_in = q * 96 + (gg - 48 * q);
            float gi = bihs[gg] + ia * tb[pos_in] + oa * tb[pos_in + 48];
            g_Gi[(size_t)gg * BN + b * NN + v] = gi;
        }
        __syncwarp();
    }
}

// ---------------------------------------------------------------------------
// Kernel B4: GRU, one row per thread, float4 shared weight loads, fully
// unrolled, low register pressure. grid 256 x 256.
// ---------------------------------------------------------------------------
__global__ void __launch_bounds__(256) step_gru4(
    const float* __restrict__ w_hh, const float* __restrict__ b_hh,
    const float* __restrict__ w_fc, const float* __restrict__ b_fc,
    float* __restrict__ out, int t, float* __restrict__ h_final)
{
    __shared__ __align__(16) float whh[GG * SS];
    __shared__ float bhh[GG];
    __shared__ float wfc[SS];

    int tid = threadIdx.x;
    for (int i = tid; i < GG * SS; i += 256) whh[i] = w_hh[i];
    if (tid < GG) bhh[tid] = b_hh[tid];
    if (tid < SS) wfc[tid] = w_fc[tid];
    __syncthreads();

    const float4* whh4 = reinterpret_cast<const float4*>(whh);

    int r = blockIdx.x * 256 + tid;

    float h[SS];
    {
        const float4* hp = reinterpret_cast<const float4*>(g_h + (size_t)r * SS);
        #pragma unroll
        for (int q = 0; q < 8; q++) {
            float4 hv = hp[q];
            h[q * 4 + 0] = hv.x; h[q * 4 + 1] = hv.y;
            h[q * 4 + 2] = hv.z; h[q * 4 + 3] = hv.w;
        }
    }

    float4* hrow  = reinterpret_cast<float4*>(g_h + (size_t)r * SS);
    float4* hfrow = h_final ? reinterpret_cast<float4*>(h_final + (size_t)r * SS)
                            : nullptr;

    float fc = 0.0f;
    float o0, o1, o2, o3;

    #pragma unroll
    for (int d = 0; d < SS; d++) {
        float ar = bhh[d], az = bhh[SS + d], an = bhh[2 * SS + d];
        #pragma unroll
        for (int q = 0; q < 8; q++) {
            float4 wr = whh4[(d * SS) / 4 + q];
            float4 wz = whh4[((SS + d) * SS) / 4 + q];
            float4 wn = whh4[((2 * SS + d) * SS) / 4 + q];
            float h0 = h[q * 4 + 0], h1 = h[q * 4 + 1];
            float h2 = h[q * 4 + 2], h3 = h[q * 4 + 3];
            ar += wr.x * h0 + wr.y * h1 + wr.z * h2 + wr.w * h3;
            az += wz.x * h0 + wz.y * h1 + wz.z * h2 + wz.w * h3;
            an += wn.x * h0 + wn.y * h1 + wn.z * h2 + wn.w * h3;
        }
        float gr = g_Gi[(size_t)d * BN + r];
        float gz = g_Gi[(size_t)(SS + d) * BN + r];
        float gn = g_Gi[(size_t)(2 * SS + d) * BN + r];
        float rr = sigmf(ar + gr);
        float zz = sigmf(az + gz);
        float nn = tanhfast(gn + rr * an);
        float hn = (1.0f - zz) * nn + zz * h[d];
        fc += hn * wfc[d];
        if ((d & 3) == 0) o0 = hn;
        else if ((d & 3) == 1) o1 = hn;
        else if ((d & 3) == 2) o2 = hn;
        else {
            o3 = hn;
            float4 ov; ov.x = o0; ov.y = o1; ov.z = o2; ov.w = o3;
            hrow[d / 4] = ov;
            if (hfrow) hfrow[d / 4] = ov;
        }
    }

    int b0 = r >> 10;
    int v0 = r & (NN - 1);
    out[((size_t)b0 * TT + t) * NN + v0] = sigmf(fc + b_fc[0]);
}

// ---------------------------------------------------------------------------
extern "C" void kernel_launch(void* const* d_in, const int* in_sizes, int n_in,
                              void* d_out, int out_size) {
    const int*   item_ids  = (const int*)  d_in[0];
    const int*   responses = (const int*)  d_in[1];
    const float* adj       = (const float*)d_in[2];
    const float* item_emb  = (const float*)d_in[3];
    const float* resp_emb  = (const float*)d_in[4];
    const float* w_in      = (const float*)d_in[5];
    const float* b_in      = (const float*)d_in[6];
    const float* w_out     = (const float*)d_in[7];
    const float* b_out     = (const float*)d_in[8];
    const float* in_a      = (const float*)d_in[9];
    const float* out_a     = (const float*)d_in[10];
    const float* w_ih      = (const float*)d_in[11];
    const float* w_hh      = (const float*)d_in[12];
    const float* b_ih      = (const float*)d_in[13];
    const float* b_hh      = (const float*)d_in[14];
    const float* w_fc      = (const float*)d_in[15];
    const float* b_fc      = (const float*)d_in[16];

    float* out    = (float*)d_out;                       // (B, T, N)
    float* h_out  = out + (size_t)NB * TT * NN;          // (B, N, S)

    cudaFuncSetAttribute(step_sparse3,
                         cudaFuncAttributeMaxDynamicSharedMemorySize,
                         SP3_SMEM_BYTES);

    build_csc_kernel<<<NN, 256>>>(adj);
    build_cn_kernel<<<NN, 32>>>(item_emb);
    build_M_kernel<<<192, 128>>>(w_ih, w_in, w_out);
    build_Pc_kernel<<<NN / 16, 192>>>(item_emb, w_ih, b_in, b_out);
    {
        int total = GG * BN;
        init_state_kernel<<<(total + 255) / 256, 256>>>(b_ih);
    }

    for (int t = 0; t < TT; t++) {
        step_sparse3<<<NB, 512, SP3_SMEM_BYTES>>>(
            item_ids, responses, t, adj, item_emb, resp_emb,
            in_a, out_a, b_ih);
        step_gru4<<<BN / 256, 256>>>(
            w_hh, b_hh, w_fc, b_fc, out, t,
            (t == TT - 1) ? h_out : nullptr);
    }
}